// round 2
// baseline (speedup 1.0000x reference)
#include <cuda_runtime.h>
#include <cstdint>

#define B_  2
#define S_  2048
#define D_  1024
#define H_  16
#define DK_ 64
#define NEGV -1.0e9f

// Scratch (allocation-free rule: __device__ globals)
__device__ float g_q[B_ * S_ * D_];
__device__ float g_k[B_ * S_ * D_];
__device__ float g_v[B_ * S_ * D_];
__device__ float g_ctx[B_ * S_ * D_];

// ---------------------------------------------------------------------------
// GEMM: C[M,N] = A[M,K] @ B[N,K]^T + bias[N]   (fp32, NT)
// BM=BN=128, BK=16, 256 threads, 8x8 register tile per thread.
// ---------------------------------------------------------------------------
__global__ __launch_bounds__(256) void gemm_nt_bias(
    const float* __restrict__ A, const float* __restrict__ Bw,
    const float* __restrict__ bias, float* __restrict__ C,
    int M, int N, int K)
{
    const int BK = 16;
    __shared__ float As[BK][128 + 4];   // [k][m]
    __shared__ float Bs[BK][128 + 4];   // [k][n]

    const int tx = threadIdx.x, ty = threadIdx.y;
    const int tid = ty * 16 + tx;
    const int m0 = blockIdx.y * 128;
    const int n0 = blockIdx.x * 128;

    const int lr = tid >> 1;          // 0..127 (row within tile)
    const int lc = (tid & 1) * 8;     // 0 or 8 (k offset)

    float acc[8][8];
#pragma unroll
    for (int i = 0; i < 8; i++)
#pragma unroll
        for (int j = 0; j < 8; j++) acc[i][j] = 0.f;

    for (int kt = 0; kt < K; kt += BK) {
        // Stage A tile (transposed: [k][m])
        {
            const float* p = &A[(size_t)(m0 + lr) * K + kt + lc];
            float4 a0 = *(const float4*)p;
            float4 a1 = *(const float4*)(p + 4);
            As[lc + 0][lr] = a0.x; As[lc + 1][lr] = a0.y;
            As[lc + 2][lr] = a0.z; As[lc + 3][lr] = a0.w;
            As[lc + 4][lr] = a1.x; As[lc + 5][lr] = a1.y;
            As[lc + 6][lr] = a1.z; As[lc + 7][lr] = a1.w;
        }
        // Stage B tile (transposed: [k][n])
        {
            const float* p = &Bw[(size_t)(n0 + lr) * K + kt + lc];
            float4 b0 = *(const float4*)p;
            float4 b1 = *(const float4*)(p + 4);
            Bs[lc + 0][lr] = b0.x; Bs[lc + 1][lr] = b0.y;
            Bs[lc + 2][lr] = b0.z; Bs[lc + 3][lr] = b0.w;
            Bs[lc + 4][lr] = b1.x; Bs[lc + 5][lr] = b1.y;
            Bs[lc + 6][lr] = b1.z; Bs[lc + 7][lr] = b1.w;
        }
        __syncthreads();

#pragma unroll
        for (int k = 0; k < BK; k++) {
            float4 x0 = *(const float4*)&As[k][ty * 8];
            float4 x1 = *(const float4*)&As[k][ty * 8 + 4];
            float4 y0 = *(const float4*)&Bs[k][tx * 8];
            float4 y1 = *(const float4*)&Bs[k][tx * 8 + 4];
            float xa[8] = {x0.x, x0.y, x0.z, x0.w, x1.x, x1.y, x1.z, x1.w};
            float yb[8] = {y0.x, y0.y, y0.z, y0.w, y1.x, y1.y, y1.z, y1.w};
#pragma unroll
            for (int i = 0; i < 8; i++)
#pragma unroll
                for (int j = 0; j < 8; j++)
                    acc[i][j] += xa[i] * yb[j];
        }
        __syncthreads();
    }

    // Epilogue: bias + store (vectorized)
    const int nbase = n0 + tx * 8;
    float4 bi0 = *(const float4*)&bias[nbase];
    float4 bi1 = *(const float4*)&bias[nbase + 4];
    float bb[8] = {bi0.x, bi0.y, bi0.z, bi0.w, bi1.x, bi1.y, bi1.z, bi1.w};
#pragma unroll
    for (int i = 0; i < 8; i++) {
        const int row = m0 + ty * 8 + i;
        float4 c0, c1;
        c0.x = acc[i][0] + bb[0]; c0.y = acc[i][1] + bb[1];
        c0.z = acc[i][2] + bb[2]; c0.w = acc[i][3] + bb[3];
        c1.x = acc[i][4] + bb[4]; c1.y = acc[i][5] + bb[5];
        c1.z = acc[i][6] + bb[6]; c1.w = acc[i][7] + bb[7];
        *(float4*)&C[(size_t)row * N + nbase] = c0;
        *(float4*)&C[(size_t)row * N + nbase + 4] = c1;
    }
}

// ---------------------------------------------------------------------------
// Flash attention: one CTA = (b, h, 64 q-rows). Streams 64-key tiles.
// 256 threads (16x16); score tile 64x64 (4x4 regs/thread); O 64x64 (4x4/thread).
// ---------------------------------------------------------------------------
__global__ __launch_bounds__(256) void flash_kernel(
    const float* __restrict__ Q, const float* __restrict__ K,
    const float* __restrict__ V, const int* __restrict__ mask,
    float* __restrict__ ctx)
{
    const int ST = 68;  // padded stride
    extern __shared__ float sm[];
    float* Qs  = sm;             // [d][m]  64x68
    float* Kt  = Qs + 64 * ST;   // [d][n]  64x68
    float* Vs  = Kt + 64 * ST;   // [n][d]  64x68
    float* Ss  = Vs + 64 * ST;   // [m][n]  64x68
    float* m_s = Ss + 64 * ST;   // [64]
    float* l_s = m_s + 64;       // [64]
    float* al_s = l_s + 64;      // [64]

    const int tx = threadIdx.x, ty = threadIdx.y;
    const int tid = ty * 16 + tx;
    const int b = blockIdx.z, h = blockIdx.y;
    const int q0 = blockIdx.x * 64;

    const float* Qb = Q + ((size_t)b * S_ + q0) * D_ + h * DK_;
    const float* Kb = K + (size_t)b * S_ * D_ + h * DK_;
    const float* Vb = V + (size_t)b * S_ * D_ + h * DK_;
    const int*   Mb = mask + (size_t)b * S_ * S_ + (size_t)q0 * S_;

    // Load Q tile (transposed), fold 1/sqrt(dk) = 0.125
#pragma unroll 4
    for (int e = tid; e < 64 * 64; e += 256) {
        int r = e >> 6, d = e & 63;
        Qs[d * ST + r] = Qb[(size_t)r * D_ + d] * 0.125f;
    }
    if (tid < 64) { m_s[tid] = -3.0e38f; l_s[tid] = 0.f; }

    float O[4][4];
#pragma unroll
    for (int i = 0; i < 4; i++)
#pragma unroll
        for (int j = 0; j < 4; j++) O[i][j] = 0.f;

    for (int kt = 0; kt < S_; kt += 64) {
        __syncthreads();  // protect Kt/Vs from previous iteration's readers
        // Stage K (transposed) and V (natural)
#pragma unroll 4
        for (int e = tid; e < 64 * 64; e += 256) {
            int r = e >> 6, d = e & 63;
            float kval = Kb[(size_t)(kt + r) * D_ + d];
            float vval = Vb[(size_t)(kt + r) * D_ + d];
            Kt[d * ST + r] = kval;
            Vs[r * ST + d] = vval;
        }
        __syncthreads();

        // S = (Q*scale) @ K^T  — 4x4 per thread over 64-deep reduction
        float s[4][4];
#pragma unroll
        for (int i = 0; i < 4; i++)
#pragma unroll
            for (int j = 0; j < 4; j++) s[i][j] = 0.f;

#pragma unroll 8
        for (int d = 0; d < 64; d++) {
            float4 qa = *(const float4*)&Qs[d * ST + ty * 4];
            float4 kb = *(const float4*)&Kt[d * ST + tx * 4];
            float qv[4] = {qa.x, qa.y, qa.z, qa.w};
            float kv[4] = {kb.x, kb.y, kb.z, kb.w};
#pragma unroll
            for (int i = 0; i < 4; i++)
#pragma unroll
                for (int j = 0; j < 4; j++)
                    s[i][j] += qv[i] * kv[j];
        }

        // Apply mask, write score tile to smem
#pragma unroll
        for (int i = 0; i < 4; i++) {
            int m = ty * 4 + i;
            int4 mk = *(const int4*)&Mb[(size_t)m * S_ + kt + tx * 4];
            float4 w;
            w.x = mk.x ? s[i][0] : NEGV;
            w.y = mk.y ? s[i][1] : NEGV;
            w.z = mk.z ? s[i][2] : NEGV;
            w.w = mk.w ? s[i][3] : NEGV;
            *(float4*)&Ss[m * ST + tx * 4] = w;
        }
        __syncthreads();

        // Online softmax: 4 threads per row (consecutive lanes -> shfl works)
        {
            int r = tid >> 2, part = tid & 3;
            float* row = &Ss[r * ST + part * 16];
            float mx = row[0];
#pragma unroll
            for (int c = 1; c < 16; c++) mx = fmaxf(mx, row[c]);
            mx = fmaxf(mx, __shfl_xor_sync(0xffffffffu, mx, 1));
            mx = fmaxf(mx, __shfl_xor_sync(0xffffffffu, mx, 2));
            float mprev = m_s[r];
            float mnew = fmaxf(mprev, mx);
            float alpha = __expf(mprev - mnew);
            float sum = 0.f;
#pragma unroll
            for (int c = 0; c < 16; c++) {
                float p = __expf(row[c] - mnew);
                row[c] = p;
                sum += p;
            }
            sum += __shfl_xor_sync(0xffffffffu, sum, 1);
            sum += __shfl_xor_sync(0xffffffffu, sum, 2);
            if (part == 0) {
                m_s[r] = mnew;
                l_s[r] = l_s[r] * alpha + sum;
                al_s[r] = alpha;
            }
        }
        __syncthreads();

        // Rescale O, accumulate P @ V
        float al[4];
#pragma unroll
        for (int i = 0; i < 4; i++) al[i] = al_s[ty * 4 + i];
#pragma unroll
        for (int i = 0; i < 4; i++)
#pragma unroll
            for (int j = 0; j < 4; j++) O[i][j] *= al[i];

#pragma unroll 4
        for (int n = 0; n < 64; n++) {
            float4 vv = *(const float4*)&Vs[n * ST + tx * 4];
            float vb4[4] = {vv.x, vv.y, vv.z, vv.w};
            float p0 = Ss[(ty * 4 + 0) * ST + n];
            float p1 = Ss[(ty * 4 + 1) * ST + n];
            float p2 = Ss[(ty * 4 + 2) * ST + n];
            float p3 = Ss[(ty * 4 + 3) * ST + n];
#pragma unroll
            for (int j = 0; j < 4; j++) {
                O[0][j] += p0 * vb4[j];
                O[1][j] += p1 * vb4[j];
                O[2][j] += p2 * vb4[j];
                O[3][j] += p3 * vb4[j];
            }
        }
    }

    // Final normalize + store (ctx layout = concat-heads [B,S,D])
    float rinv[4];
#pragma unroll
    for (int i = 0; i < 4; i++) rinv[i] = 1.f / l_s[ty * 4 + i];
    float* Cb = ctx + ((size_t)b * S_ + q0) * D_ + h * DK_;
#pragma unroll
    for (int i = 0; i < 4; i++) {
        float4 w;
        w.x = O[i][0] * rinv[i];
        w.y = O[i][1] * rinv[i];
        w.z = O[i][2] * rinv[i];
        w.w = O[i][3] * rinv[i];
        *(float4*)&Cb[(size_t)(ty * 4 + i) * D_ + tx * 4] = w;
    }
}

// ---------------------------------------------------------------------------
// Launch
// Inputs (metadata order): query, key, value, mask, w_q, b_q, w_k, b_k,
//                          w_v, b_v, w_o, b_o
// ---------------------------------------------------------------------------
extern "C" void kernel_launch(void* const* d_in, const int* in_sizes, int n_in,
                              void* d_out, int out_size)
{
    const float* query = (const float*)d_in[0];
    const float* key   = (const float*)d_in[1];
    const float* value = (const float*)d_in[2];
    const int*   mask  = (const int*)d_in[3];
    const float* w_q = (const float*)d_in[4];
    const float* b_q = (const float*)d_in[5];
    const float* w_k = (const float*)d_in[6];
    const float* b_k = (const float*)d_in[7];
    const float* w_v = (const float*)d_in[8];
    const float* b_v = (const float*)d_in[9];
    const float* w_o = (const float*)d_in[10];
    const float* b_o = (const float*)d_in[11];

    float *gq, *gk, *gv, *gc;
    cudaGetSymbolAddress((void**)&gq, g_q);
    cudaGetSymbolAddress((void**)&gk, g_k);
    cudaGetSymbolAddress((void**)&gv, g_v);
    cudaGetSymbolAddress((void**)&gc, g_ctx);

    const size_t flash_smem = (4 * 64 * 68 + 192) * sizeof(float);  // 70400 B
    cudaFuncSetAttribute(flash_kernel,
                         cudaFuncAttributeMaxDynamicSharedMemorySize,
                         (int)flash_smem);

    dim3 blk(16, 16);
    const int M = B_ * S_;                        // 4096
    dim3 gproj(D_ / 128, M / 128);                // (8, 32)

    gemm_nt_bias<<<gproj, blk>>>(query, w_q, b_q, gq, M, D_, D_);
    gemm_nt_bias<<<gproj, blk>>>(key,   w_k, b_k, gk, M, D_, D_);
    gemm_nt_bias<<<gproj, blk>>>(value, w_v, b_v, gv, M, D_, D_);

    dim3 gflash(S_ / 64, H_, B_);                 // (32, 16, 2)
    flash_kernel<<<gflash, blk, flash_smem>>>(gq, gk, gv, mask, gc);

    gemm_nt_bias<<<gproj, blk>>>(gc, w_o, b_o, (float*)d_out, M, D_, D_);
}

// round 3
// speedup vs baseline: 1.0003x; 1.0003x over previous
#include <cuda_runtime.h>
#include <cstdint>

#define B_  2
#define S_  2048
#define D_  1024
#define H_  16
#define DK_ 64
#define NEGV -1.0e9f

// Scratch (allocation-free rule: __device__ globals)
__device__ float g_q[B_ * S_ * D_];
__device__ float g_k[B_ * S_ * D_];
__device__ float g_v[B_ * S_ * D_];
__device__ float g_ctx[B_ * S_ * D_];

// ---------------------------------------------------------------------------
// GEMM: C[M,N] = A[M,K] @ B[N,K]^T + bias[N]   (fp32, NT)
// BM=BN=128, BK=16, 256 threads, 8x8 register tile per thread.
// ---------------------------------------------------------------------------
__global__ __launch_bounds__(256) void gemm_nt_bias(
    const float* __restrict__ A, const float* __restrict__ Bw,
    const float* __restrict__ bias, float* __restrict__ C,
    int M, int N, int K)
{
    const int BK = 16;
    __shared__ float As[BK][128 + 4];   // [k][m]
    __shared__ float Bs[BK][128 + 4];   // [k][n]

    const int tx = threadIdx.x, ty = threadIdx.y;
    const int tid = ty * 16 + tx;
    const int m0 = blockIdx.y * 128;
    const int n0 = blockIdx.x * 128;

    const int lr = tid >> 1;          // 0..127 (row within tile)
    const int lc = (tid & 1) * 8;     // 0 or 8 (k offset)

    float acc[8][8];
#pragma unroll
    for (int i = 0; i < 8; i++)
#pragma unroll
        for (int j = 0; j < 8; j++) acc[i][j] = 0.f;

    for (int kt = 0; kt < K; kt += BK) {
        // Stage A tile (transposed: [k][m])
        {
            const float* p = &A[(size_t)(m0 + lr) * K + kt + lc];
            float4 a0 = *(const float4*)p;
            float4 a1 = *(const float4*)(p + 4);
            As[lc + 0][lr] = a0.x; As[lc + 1][lr] = a0.y;
            As[lc + 2][lr] = a0.z; As[lc + 3][lr] = a0.w;
            As[lc + 4][lr] = a1.x; As[lc + 5][lr] = a1.y;
            As[lc + 6][lr] = a1.z; As[lc + 7][lr] = a1.w;
        }
        // Stage B tile (transposed: [k][n])
        {
            const float* p = &Bw[(size_t)(n0 + lr) * K + kt + lc];
            float4 b0 = *(const float4*)p;
            float4 b1 = *(const float4*)(p + 4);
            Bs[lc + 0][lr] = b0.x; Bs[lc + 1][lr] = b0.y;
            Bs[lc + 2][lr] = b0.z; Bs[lc + 3][lr] = b0.w;
            Bs[lc + 4][lr] = b1.x; Bs[lc + 5][lr] = b1.y;
            Bs[lc + 6][lr] = b1.z; Bs[lc + 7][lr] = b1.w;
        }
        __syncthreads();

#pragma unroll
        for (int k = 0; k < BK; k++) {
            float4 x0 = *(const float4*)&As[k][ty * 8];
            float4 x1 = *(const float4*)&As[k][ty * 8 + 4];
            float4 y0 = *(const float4*)&Bs[k][tx * 8];
            float4 y1 = *(const float4*)&Bs[k][tx * 8 + 4];
            float xa[8] = {x0.x, x0.y, x0.z, x0.w, x1.x, x1.y, x1.z, x1.w};
            float yb[8] = {y0.x, y0.y, y0.z, y0.w, y1.x, y1.y, y1.z, y1.w};
#pragma unroll
            for (int i = 0; i < 8; i++)
#pragma unroll
                for (int j = 0; j < 8; j++)
                    acc[i][j] += xa[i] * yb[j];
        }
        __syncthreads();
    }

    // Epilogue: bias + store (vectorized)
    const int nbase = n0 + tx * 8;
    float4 bi0 = *(const float4*)&bias[nbase];
    float4 bi1 = *(const float4*)&bias[nbase + 4];
    float bb[8] = {bi0.x, bi0.y, bi0.z, bi0.w, bi1.x, bi1.y, bi1.z, bi1.w};
#pragma unroll
    for (int i = 0; i < 8; i++) {
        const int row = m0 + ty * 8 + i;
        float4 c0, c1;
        c0.x = acc[i][0] + bb[0]; c0.y = acc[i][1] + bb[1];
        c0.z = acc[i][2] + bb[2]; c0.w = acc[i][3] + bb[3];
        c1.x = acc[i][4] + bb[4]; c1.y = acc[i][5] + bb[5];
        c1.z = acc[i][6] + bb[6]; c1.w = acc[i][7] + bb[7];
        *(float4*)&C[(size_t)row * N + nbase] = c0;
        *(float4*)&C[(size_t)row * N + nbase + 4] = c1;
    }
}

// ---------------------------------------------------------------------------
// Flash attention: one CTA = (b, h, 64 q-rows). Streams 64-key tiles.
// 256 threads (16x16); score tile 64x64 (4x4 regs/thread); O 64x64 (4x4/thread).
// ---------------------------------------------------------------------------
__global__ __launch_bounds__(256) void flash_kernel(
    const float* __restrict__ Q, const float* __restrict__ K,
    const float* __restrict__ V, const int* __restrict__ mask,
    float* __restrict__ ctx)
{
    const int ST = 68;  // padded stride
    extern __shared__ float sm[];
    float* Qs  = sm;             // [d][m]  64x68
    float* Kt  = Qs + 64 * ST;   // [d][n]  64x68
    float* Vs  = Kt + 64 * ST;   // [n][d]  64x68
    float* Ss  = Vs + 64 * ST;   // [m][n]  64x68
    float* m_s = Ss + 64 * ST;   // [64]
    float* l_s = m_s + 64;       // [64]
    float* al_s = l_s + 64;      // [64]

    const int tx = threadIdx.x, ty = threadIdx.y;
    const int tid = ty * 16 + tx;
    const int b = blockIdx.z, h = blockIdx.y;
    const int q0 = blockIdx.x * 64;

    const float* Qb = Q + ((size_t)b * S_ + q0) * D_ + h * DK_;
    const float* Kb = K + (size_t)b * S_ * D_ + h * DK_;
    const float* Vb = V + (size_t)b * S_ * D_ + h * DK_;
    const int*   Mb = mask + (size_t)b * S_ * S_ + (size_t)q0 * S_;

    // Load Q tile (transposed), fold 1/sqrt(dk) = 0.125
#pragma unroll 4
    for (int e = tid; e < 64 * 64; e += 256) {
        int r = e >> 6, d = e & 63;
        Qs[d * ST + r] = Qb[(size_t)r * D_ + d] * 0.125f;
    }
    if (tid < 64) { m_s[tid] = -3.0e38f; l_s[tid] = 0.f; }

    float O[4][4];
#pragma unroll
    for (int i = 0; i < 4; i++)
#pragma unroll
        for (int j = 0; j < 4; j++) O[i][j] = 0.f;

    for (int kt = 0; kt < S_; kt += 64) {
        __syncthreads();  // protect Kt/Vs from previous iteration's readers
        // Stage K (transposed) and V (natural)
#pragma unroll 4
        for (int e = tid; e < 64 * 64; e += 256) {
            int r = e >> 6, d = e & 63;
            float kval = Kb[(size_t)(kt + r) * D_ + d];
            float vval = Vb[(size_t)(kt + r) * D_ + d];
            Kt[d * ST + r] = kval;
            Vs[r * ST + d] = vval;
        }
        __syncthreads();

        // S = (Q*scale) @ K^T  — 4x4 per thread over 64-deep reduction
        float s[4][4];
#pragma unroll
        for (int i = 0; i < 4; i++)
#pragma unroll
            for (int j = 0; j < 4; j++) s[i][j] = 0.f;

#pragma unroll 8
        for (int d = 0; d < 64; d++) {
            float4 qa = *(const float4*)&Qs[d * ST + ty * 4];
            float4 kb = *(const float4*)&Kt[d * ST + tx * 4];
            float qv[4] = {qa.x, qa.y, qa.z, qa.w};
            float kv[4] = {kb.x, kb.y, kb.z, kb.w};
#pragma unroll
            for (int i = 0; i < 4; i++)
#pragma unroll
                for (int j = 0; j < 4; j++)
                    s[i][j] += qv[i] * kv[j];
        }

        // Apply mask, write score tile to smem
#pragma unroll
        for (int i = 0; i < 4; i++) {
            int m = ty * 4 + i;
            int4 mk = *(const int4*)&Mb[(size_t)m * S_ + kt + tx * 4];
            float4 w;
            w.x = mk.x ? s[i][0] : NEGV;
            w.y = mk.y ? s[i][1] : NEGV;
            w.z = mk.z ? s[i][2] : NEGV;
            w.w = mk.w ? s[i][3] : NEGV;
            *(float4*)&Ss[m * ST + tx * 4] = w;
        }
        __syncthreads();

        // Online softmax: 4 threads per row (consecutive lanes -> shfl works)
        {
            int r = tid >> 2, part = tid & 3;
            float* row = &Ss[r * ST + part * 16];
            float mx = row[0];
#pragma unroll
            for (int c = 1; c < 16; c++) mx = fmaxf(mx, row[c]);
            mx = fmaxf(mx, __shfl_xor_sync(0xffffffffu, mx, 1));
            mx = fmaxf(mx, __shfl_xor_sync(0xffffffffu, mx, 2));
            float mprev = m_s[r];
            float mnew = fmaxf(mprev, mx);
            float alpha = __expf(mprev - mnew);
            float sum = 0.f;
#pragma unroll
            for (int c = 0; c < 16; c++) {
                float p = __expf(row[c] - mnew);
                row[c] = p;
                sum += p;
            }
            sum += __shfl_xor_sync(0xffffffffu, sum, 1);
            sum += __shfl_xor_sync(0xffffffffu, sum, 2);
            if (part == 0) {
                m_s[r] = mnew;
                l_s[r] = l_s[r] * alpha + sum;
                al_s[r] = alpha;
            }
        }
        __syncthreads();

        // Rescale O, accumulate P @ V
        float al[4];
#pragma unroll
        for (int i = 0; i < 4; i++) al[i] = al_s[ty * 4 + i];
#pragma unroll
        for (int i = 0; i < 4; i++)
#pragma unroll
            for (int j = 0; j < 4; j++) O[i][j] *= al[i];

#pragma unroll 4
        for (int n = 0; n < 64; n++) {
            float4 vv = *(const float4*)&Vs[n * ST + tx * 4];
            float vb4[4] = {vv.x, vv.y, vv.z, vv.w};
            float p0 = Ss[(ty * 4 + 0) * ST + n];
            float p1 = Ss[(ty * 4 + 1) * ST + n];
            float p2 = Ss[(ty * 4 + 2) * ST + n];
            float p3 = Ss[(ty * 4 + 3) * ST + n];
#pragma unroll
            for (int j = 0; j < 4; j++) {
                O[0][j] += p0 * vb4[j];
                O[1][j] += p1 * vb4[j];
                O[2][j] += p2 * vb4[j];
                O[3][j] += p3 * vb4[j];
            }
        }
    }

    // Final normalize + store (ctx layout = concat-heads [B,S,D])
    float rinv[4];
#pragma unroll
    for (int i = 0; i < 4; i++) rinv[i] = 1.f / l_s[ty * 4 + i];
    float* Cb = ctx + ((size_t)b * S_ + q0) * D_ + h * DK_;
#pragma unroll
    for (int i = 0; i < 4; i++) {
        float4 w;
        w.x = O[i][0] * rinv[i];
        w.y = O[i][1] * rinv[i];
        w.z = O[i][2] * rinv[i];
        w.w = O[i][3] * rinv[i];
        *(float4*)&Cb[(size_t)(ty * 4 + i) * D_ + tx * 4] = w;
    }
}

// ---------------------------------------------------------------------------
// Launch
// Inputs (metadata order): query, key, value, mask, w_q, b_q, w_k, b_k,
//                          w_v, b_v, w_o, b_o
// ---------------------------------------------------------------------------
extern "C" void kernel_launch(void* const* d_in, const int* in_sizes, int n_in,
                              void* d_out, int out_size)
{
    const float* query = (const float*)d_in[0];
    const float* key   = (const float*)d_in[1];
    const float* value = (const float*)d_in[2];
    const int*   mask  = (const int*)d_in[3];
    const float* w_q = (const float*)d_in[4];
    const float* b_q = (const float*)d_in[5];
    const float* w_k = (const float*)d_in[6];
    const float* b_k = (const float*)d_in[7];
    const float* w_v = (const float*)d_in[8];
    const float* b_v = (const float*)d_in[9];
    const float* w_o = (const float*)d_in[10];
    const float* b_o = (const float*)d_in[11];

    float *gq, *gk, *gv, *gc;
    cudaGetSymbolAddress((void**)&gq, g_q);
    cudaGetSymbolAddress((void**)&gk, g_k);
    cudaGetSymbolAddress((void**)&gv, g_v);
    cudaGetSymbolAddress((void**)&gc, g_ctx);

    const size_t flash_smem = (4 * 64 * 68 + 192) * sizeof(float);  // 70400 B
    cudaFuncSetAttribute(flash_kernel,
                         cudaFuncAttributeMaxDynamicSharedMemorySize,
                         (int)flash_smem);

    dim3 blk(16, 16);
    const int M = B_ * S_;                        // 4096
    dim3 gproj(D_ / 128, M / 128);                // (8, 32)

    gemm_nt_bias<<<gproj, blk>>>(query, w_q, b_q, gq, M, D_, D_);
    gemm_nt_bias<<<gproj, blk>>>(key,   w_k, b_k, gk, M, D_, D_);
    gemm_nt_bias<<<gproj, blk>>>(value, w_v, b_v, gv, M, D_, D_);

    dim3 gflash(S_ / 64, H_, B_);                 // (32, 16, 2)
    flash_kernel<<<gflash, blk, flash_smem>>>(gq, gk, gv, mask, gc);

    gemm_nt_bias<<<gproj, blk>>>(gc, w_o, b_o, (float*)d_out, M, D_, D_);
}